// round 14
// baseline (speedup 1.0000x reference)
#include <cuda_runtime.h>
#include <cuda_fp16.h>
#include <cstdint>
#include <math_constants.h>

// ---------------- problem constants ----------------
constexpr int B_   = 16;
constexpr int NH   = 8;
constexpr int NQ   = 1569;   // 8*14*14 + 1
constexpr int NKV  = 393;    // 8*7*7 + 1
constexpr int HDc  = 96;
constexpr int DIMc = 768;
constexpr int LQ   = 1568;
constexpr int MROWS = B_ * NQ;     // 25104
constexpr int QPAD = 1664;         // 13 * 128
constexpr int KPAD = 448;          // 7 * 64
constexpr float SCALE = 0.10206207261596577f;  // 96^-0.5

// ---------------- scratch (device globals; zero-initialized, no allocs) -----
__device__ float g_q [B_*NH*NQ*HDc];
__device__ float g_k [B_*NH*NQ*HDc];
__device__ float g_v [B_*NH*NQ*HDc];
__device__ float g_qp[B_*NH*NQ*HDc];
__device__ float g_kp[B_*NH*NKV*HDc];
__device__ float g_vp[B_*NH*NKV*HDc];
__device__ __half g_x16 [MROWS*DIMc];
__device__ __half g_w1T [3*DIMc*DIMc];
__device__ __half g_w2T [DIMc*DIMc];
__device__ __half g_ao16[MROWS*DIMc];
__device__ __half g_qp16[B_*NH*QPAD*HDc];   // pooled q fp16 (unscaled), padded rows zero
__device__ __half g_kp16[B_*NH*KPAD*HDc];   // pooled k fp16 * SCALE, padded rows zero
__device__ __half g_vp16t[B_*NH*HDc*KPAD];  // pooled v fp16 transposed [chan][key], pad zero

__device__ __forceinline__ float4 ld4(const float* p){ return *reinterpret_cast<const float4*>(p); }

// pack two floats -> half2 bits as unsigned (for mma A-fragment)
__device__ __forceinline__ unsigned pack_h2(float lo, float hi)
{
    __half2_raw hr = __floats2half2_rn(lo, hi);
    return (unsigned)hr.x | ((unsigned)hr.y << 16);
}

// ---------------- tensor-core helpers ----------------
__device__ __forceinline__ void ldsm4(unsigned int &r0, unsigned int &r1,
                                      unsigned int &r2, unsigned int &r3,
                                      const __half* p)
{
    unsigned int a = (unsigned int)__cvta_generic_to_shared(p);
    asm volatile("ldmatrix.sync.aligned.m8n8.x4.shared.b16 {%0,%1,%2,%3}, [%4];"
                 : "=r"(r0), "=r"(r1), "=r"(r2), "=r"(r3) : "r"(a));
}
__device__ __forceinline__ void mma16816(float* d, const unsigned int* a, const unsigned int* b)
{
    asm volatile("mma.sync.aligned.m16n8k16.row.col.f32.f16.f16.f32 "
                 "{%0,%1,%2,%3}, {%4,%5,%6,%7}, {%8,%9}, {%0,%1,%2,%3};"
                 : "+f"(d[0]), "+f"(d[1]), "+f"(d[2]), "+f"(d[3])
                 : "r"(a[0]), "r"(a[1]), "r"(a[2]), "r"(a[3]), "r"(b[0]), "r"(b[1]));
}
__device__ __forceinline__ void cpa16(const __half* sdst, const __half* gsrc)
{
    unsigned s = (unsigned)__cvta_generic_to_shared(sdst);
    asm volatile("cp.async.cg.shared.global [%0], [%1], 16;" :: "r"(s), "l"(gsrc) : "memory");
}
__device__ __forceinline__ void cpa_commit()
{
    asm volatile("cp.async.commit_group;" ::: "memory");
}

// ---------------- conversion kernels ----------------
__global__ __launch_bounds__(256) void conv_x_kernel(const float* __restrict__ x, int n4)
{
    int i = blockIdx.x * 256 + threadIdx.x;
    if (i >= n4) return;
    float4 v = reinterpret_cast<const float4*>(x)[i];
    reinterpret_cast<__half2*>(g_x16)[2*i]   = __floats2half2_rn(v.x, v.y);
    reinterpret_cast<__half2*>(g_x16)[2*i+1] = __floats2half2_rn(v.z, v.w);
}

// merged transpose-convert: blocks x<72 -> qkv_w (N=2304), x>=72 -> proj_w (N=768)
__global__ __launch_bounds__(256) void convT_all_kernel(
    const float* __restrict__ w1, const float* __restrict__ w2)
{
    __shared__ float tile[32][33];
    const int xb = blockIdx.x;
    const float* w;
    __half* wt;
    int N, n0;
    if (xb < 72) { w = w1; wt = g_w1T; N = 2304; n0 = xb * 32; }
    else         { w = w2; wt = g_w2T; N = 768;  n0 = (xb - 72) * 32; }
    int k0 = blockIdx.y * 32;
    int tx = threadIdx.x & 31, ty = (threadIdx.x >> 5) * 4;
#pragma unroll
    for (int i = 0; i < 4; i++)
        tile[ty + i][tx] = w[(size_t)(k0 + ty + i) * N + n0 + tx];
    __syncthreads();
#pragma unroll
    for (int i = 0; i < 4; i++)
        wt[(size_t)(n0 + ty + i) * 768 + k0 + tx] = __float2half(tile[tx][ty + i]);
}

// ============================================================
// fp16 tensor-core GEMM (R9 configuration: 2-stage cp.async,
// static smem, K-tile 32, 2 CTAs/SM) — measured best (369us qkv)
// ============================================================
template<int MODE>
__device__ __forceinline__ void gemm16_body(const float* __restrict__ bias, float* __restrict__ C)
{
    __shared__ __half As[2][128*40];
    __shared__ __half Bs[2][128*40];
    const __half* A  = (MODE == 0) ? g_x16 : g_ao16;
    const __half* BT = (MODE == 0) ? g_w1T : g_w2T;
    const int t = threadIdx.x;
    const int n0 = blockIdx.x * 128, m0 = blockIdx.y * 128;
    const int w = t >> 5, lane = t & 31;
    const int wr = w >> 1, wc = w & 1;
    const int arow = t >> 1, aseg = t & 1;

    const __half* Ag = A + (size_t)min(m0 + arow, MROWS - 1) * 768 + aseg * 16;
    const __half* Bg = BT + (size_t)(n0 + arow) * 768 + aseg * 16;
    __half* Adst = &As[0][0] + arow * 40 + aseg * 16;
    __half* Bdst = &Bs[0][0] + arow * 40 + aseg * 16;

    const int a_m = (lane & 7) + ((lane >> 3) & 1) * 8;
    const int a_k = ((lane >> 4) & 1) * 8;
    const int b_n = (lane & 7) + ((lane >> 4) & 1) * 8;
    const int b_k = ((lane >> 3) & 1) * 8;

    cpa16(Adst, Ag);           cpa16(Adst + 8, Ag + 8);
    cpa16(Bdst, Bg);           cpa16(Bdst + 8, Bg + 8);
    cpa_commit();

    float acc[2][8][4];
#pragma unroll
    for (int i = 0; i < 2; i++)
#pragma unroll
        for (int j = 0; j < 8; j++)
#pragma unroll
            for (int r = 0; r < 4; r++) acc[i][j][r] = 0.f;

    for (int kt = 0; kt < 24; kt++) {
        asm volatile("cp.async.wait_group 0;" ::: "memory");
        __syncthreads();
        if (kt < 23) {
            const int nb = (kt + 1) & 1;
            const __half* Ap = Ag + (kt + 1) * 32;
            const __half* Bp = Bg + (kt + 1) * 32;
            __half* Ad = Adst + nb * (128 * 40);
            __half* Bd = Bdst + nb * (128 * 40);
            cpa16(Ad, Ap); cpa16(Ad + 8, Ap + 8);
            cpa16(Bd, Bp); cpa16(Bd + 8, Bp + 8);
            cpa_commit();
        }
        const __half* Ab = &As[kt & 1][0];
        const __half* Bb = &Bs[kt & 1][0];
#pragma unroll
        for (int kk = 0; kk < 32; kk += 16) {
            unsigned int af[2][4];
            ldsm4(af[0][0], af[0][1], af[0][2], af[0][3],
                  Ab + (wr*32 + a_m) * 40 + kk + a_k);
            ldsm4(af[1][0], af[1][1], af[1][2], af[1][3],
                  Ab + (wr*32 + 16 + a_m) * 40 + kk + a_k);
            unsigned int bf[8][2];
#pragma unroll
            for (int nf2 = 0; nf2 < 4; nf2++) {
                unsigned int r0, r1, r2, r3;
                ldsm4(r0, r1, r2, r3, Bb + (wc*64 + nf2*16 + b_n) * 40 + kk + b_k);
                bf[2*nf2][0] = r0; bf[2*nf2][1] = r1;
                bf[2*nf2+1][0] = r2; bf[2*nf2+1][1] = r3;
            }
#pragma unroll
            for (int mf = 0; mf < 2; mf++)
#pragma unroll
                for (int nf = 0; nf < 8; nf++)
                    mma16816(acc[mf][nf], af[mf], bf[nf]);
        }
    }

    const int mbase = m0 + wr * 32 + (lane >> 2);
    const int nbase = n0 + wc * 64 + (lane & 3) * 2;
#pragma unroll
    for (int mf = 0; mf < 2; mf++) {
#pragma unroll
        for (int nf = 0; nf < 8; nf++) {
            const int n = nbase + nf * 8;
            const float2 bv = *(const float2*)&bias[n];
#pragma unroll
            for (int hh = 0; hh < 2; hh++) {
                const int m = mbase + mf * 16 + hh * 8;
                if (m >= MROWS) continue;
                float2 v2;
                v2.x = acc[mf][nf][2*hh]   + bv.x;
                v2.y = acc[mf][nf][2*hh+1] + bv.y;
                if (MODE == 0) {
                    const int qkvi = n / 768, rem = n - qkvi * 768;
                    const int head = rem / 96, c = rem - head * 96;
                    float* dst = (qkvi == 0) ? g_q : (qkvi == 1) ? g_k : g_v;
                    const int b_ = m / 1569, nn = m - b_ * 1569;
                    *(float2*)&dst[(((size_t)b_*8 + head)*1569 + nn)*96 + c] = v2;
                } else {
                    *(float2*)&C[(size_t)m * 768 + n] = v2;
                }
            }
        }
    }
}

__global__ __launch_bounds__(256, 2) void gemm16_qkv_kernel(const float* __restrict__ bias)
{
    gemm16_body<0>(bias, 0);
}

__global__ __launch_bounds__(256, 2) void gemm16_proj_kernel(const float* __restrict__ bias,
                                                             float* __restrict__ C)
{
    gemm16_body<1>(bias, C);
}

// ============================================================
// Attention pool + LN: merged q/k/v launch, warp-per-token.
// grid.y: [0,197) -> q ; [197,247) -> k ; [247,297) -> v
// ============================================================
__global__ __launch_bounds__(256) void pool_ln_all_kernel(
    const float* __restrict__ wq, const float* __restrict__ wk, const float* __restrict__ wv,
    const float* __restrict__ gq, const float* __restrict__ bq,
    const float* __restrict__ gk, const float* __restrict__ bk,
    const float* __restrict__ gv, const float* __restrict__ bv)
{
    __shared__ float sw[96 * 27];
    __shared__ float sg[96], sb[96];
    const int bh = blockIdx.x;
    const int y  = blockIdx.y;
    const int t = threadIdx.x, warp = t >> 5, lane = t & 31;

    int sel, py0, outH, outW, stride, Nout;
    const float *w, *gamma, *beta;
    if (y < 197)      { sel = 0; py0 = y;       w = wq; gamma = gq; beta = bq; outH = 14; outW = 14; stride = 1; Nout = 1569; }
    else if (y < 247) { sel = 1; py0 = y - 197; w = wk; gamma = gk; beta = bk; outH = 7;  outW = 7;  stride = 2; Nout = 393;  }
    else              { sel = 2; py0 = y - 247; w = wv; gamma = gv; beta = bv; outH = 7;  outW = 7;  stride = 2; Nout = 393;  }

    for (int i = t; i < 96 * 27; i += 256) sw[i] = w[i];
    if (t < 96) { sg[t] = gamma[t]; sb[t] = beta[t]; }
    __syncthreads();

    const int p = py0 * 8 + warp;
    if (p >= Nout) return;

    const float* in  = (sel == 0) ? g_q : (sel == 1) ? g_k : g_v;
    float*       out = (sel == 0) ? g_qp : (sel == 1) ? g_kp : g_vp;
    const float* inb  = in  + (size_t)bh * NQ * 96;
    float*       outb = out + (size_t)bh * Nout * 96;

    const int c0 = lane, c1 = lane + 32, c2 = lane + 64;
    float v0 = 0.f, v1 = 0.f, v2 = 0.f;

    if (p == 0) {
        v0 = inb[c0]; v1 = inb[c1]; v2 = inb[c2];
    } else {
        const int HW = outH * outW;
        const int idx = p - 1;
        const int ot = idx / HW, r = idx - ot * HW;
        const int oh = r / outW, ow = r - oh * outW;
#pragma unroll
        for (int dt = 0; dt < 3; dt++) {
            int it = ot + dt - 1;
            if ((unsigned)it >= 8u) continue;
#pragma unroll
            for (int dh = 0; dh < 3; dh++) {
                int ih = oh * stride + dh - 1;
                if ((unsigned)ih >= 14u) continue;
#pragma unroll
                for (int dw = 0; dw < 3; dw++) {
                    int iw = ow * stride + dw - 1;
                    if ((unsigned)iw >= 14u) continue;
                    const float* src = inb + (size_t)(1 + (it*14 + ih)*14 + iw) * 96;
                    const int wi = dt*9 + dh*3 + dw;
                    v0 += src[c0] * sw[c0*27 + wi];
                    v1 += src[c1] * sw[c1*27 + wi];
                    v2 += src[c2] * sw[c2*27 + wi];
                }
            }
        }
    }

    float s1 = v0 + v1 + v2;
    float s2 = v0*v0 + v1*v1 + v2*v2;
#pragma unroll
    for (int off = 16; off; off >>= 1) {
        s1 += __shfl_xor_sync(0xffffffffu, s1, off);
        s2 += __shfl_xor_sync(0xffffffffu, s2, off);
    }
    const float mean = s1 * (1.f / 96.f);
    const float var  = s2 * (1.f / 96.f) - mean * mean;
    const float rstd = rsqrtf(var + 1e-5f);
    const float n0 = (v0 - mean) * rstd * sg[c0] + sb[c0];
    const float n1 = (v1 - mean) * rstd * sg[c1] + sb[c1];
    const float n2 = (v2 - mean) * rstd * sg[c2] + sb[c2];

    outb[(size_t)p * 96 + c0] = n0;
    outb[(size_t)p * 96 + c1] = n1;
    outb[(size_t)p * 96 + c2] = n2;

    if (sel == 0) {
        __half* q16 = g_qp16 + (size_t)bh * QPAD * 96 + (size_t)p * 96;
        q16[c0] = __float2half(n0); q16[c1] = __float2half(n1); q16[c2] = __float2half(n2);
    } else if (sel == 1) {
        __half* k16 = g_kp16 + (size_t)bh * KPAD * 96 + (size_t)p * 96;
        k16[c0] = __float2half(n0 * SCALE); k16[c1] = __float2half(n1 * SCALE); k16[c2] = __float2half(n2 * SCALE);
    } else {
        __half* v16 = g_vp16t + (size_t)bh * 96 * KPAD;
        v16[(size_t)c0 * KPAD + p] = __float2half(n0);
        v16[(size_t)c1 * KPAD + p] = __float2half(n1);
        v16[(size_t)c2 * KPAD + p] = __float2half(n2);
    }
}

// ============================================================
// fp16 flash attention with in-kernel rel-pos E computation.
// Double-buffered cp.async K/V pipeline (R11 layout).
// ============================================================
__global__ __launch_bounds__(256) void attn16_kernel(
    const float* __restrict__ rh, const float* __restrict__ rw, const float* __restrict__ rt)
{
    extern __shared__ __half dsm[];
    __shared__ float  sEb[128*24];
    __shared__ unsigned sTab[448];

    const int bh = blockIdx.y, b = bh >> 3, h = bh & 7;
    const int q0 = blockIdx.x * 128;
    const int t = threadIdx.x, w = t >> 5, lane = t & 31;

    for (int g = t; g < 448; g += 256) {
        unsigned v = 0;
        if (g >= 1 && g < NKV) {
            int kb = g - 1;
            int kt_ = kb / 49, r2 = kb - kt_ * 49;
            int kh_ = r2 / 7,  kw_ = r2 - kh_ * 7;
            v = (unsigned)kh_ | ((unsigned)kw_ << 8) | ((unsigned)kt_ << 16) | (1u << 24);
        }
        sTab[g] = v;
    }
    // stage Q tile into dsm (pitch 104)
    const __half* q16b = g_qp16 + (size_t)bh * QPAD * 96;
    for (int i = t; i < 128 * 12; i += 256) {
        int r = i / 12, s = i - r * 12;
        *(uint4*)&dsm[r * 104 + s * 8] = *(const uint4*)&q16b[(size_t)(q0 + r) * 96 + s * 8];
    }
    __syncthreads();

    const int a_m = (lane & 7) + ((lane >> 3) & 1) * 8;
    const int a_k = ((lane >> 4) & 1) * 8;
    const int b_n = (lane & 7) + ((lane >> 4) & 1) * 8;
    const int b_k = ((lane >> 3) & 1) * 8;

    unsigned aq[6][4];
#pragma unroll
    for (int kk = 0; kk < 6; kk++)
        ldsm4(aq[kk][0], aq[kk][1], aq[kk][2], aq[kk][3],
              &dsm[(w * 16 + a_m) * 104 + kk * 16 + a_k]);

    // compute E tile from staged Q (replaces the separate ebias kernel)
    for (int idx = t; idx < 128 * 22; idx += 256) {
        int q = idx / 22, e = idx - q * 22;
        int qg = q0 + q;
        float s = 0.f;
        if (qg >= 1 && qg < NQ) {
            int p = qg - 1;
            int tq_ = p / 196, r = p - tq_ * 196;
            int hh = r / 14, ww = r - hh * 14;
            const float* rr;
            if (e < 7)       rr = rh + (hh - 2*e + 12) * 96;
            else if (e < 14) rr = rw + (ww - 2*(e-7) + 12) * 96;
            else             rr = rt + (tq_ - (e-14) + 7) * 96;
            const __half2* q2 = (const __half2*)&dsm[q * 104];
#pragma unroll 8
            for (int c = 0; c < 48; c++) {
                float2 rv = *(const float2*)&rr[2*c];
                float2 qv = __half22float2(q2[c]);
                s += qv.x * rv.x + qv.y * rv.y;
            }
        }
        sEb[q * 24 + e] = s;
    }
    __syncthreads();   // Q reads (aq + E) done; dsm reusable for K/Vt

    const int r0 = w * 16 + (lane >> 2);
    const int r1 = r0 + 8;
    const int cbase = (lane & 3) * 2;

    float m0 = -CUDART_INF_F, m1 = -CUDART_INF_F, l0 = 0.f, l1 = 0.f;
    float o[12][4];
#pragma unroll
    for (int i = 0; i < 12; i++)
#pragma unroll
        for (int j = 0; j < 4; j++) o[i][j] = 0.f;

    const __half* k16b = g_kp16 + (size_t)bh * KPAD * 96;
    const __half* v16b = g_vp16t + (size_t)bh * 96 * KPAD;

#pragma unroll
    for (int pi = 0; pi < 2; pi++) {
        const int k0 = pi * 64;
        __half* sKb  = dsm + pi * 6656;
        __half* sVb  = dsm + 13312 + pi * 6912;
        for (int j = t; j < 1536; j += 256) {
            if (j < 768) {
                int r = j / 12, c = j - r * 12;
                cpa16(sKb + r * 104 + c * 8, k16b + (size_t)(k0 + r) * 96 + c * 8);
            } else {
                int q = j - 768; int r = q >> 3, c = q & 7;
                cpa16(sVb + r * 72 + c * 8, v16b + (size_t)r * KPAD + k0 + c * 8);
            }
        }
        cpa_commit();
    }

    for (int i = 0; i < 7; i++) {
        if (i == 6) asm volatile("cp.async.wait_group 0;" ::: "memory");
        else        asm volatile("cp.async.wait_group 1;" ::: "memory");
        __syncthreads();
        const int bf = i & 1;
        const __half* sK  = dsm + bf * 6656;
        const __half* sVt = dsm + 13312 + bf * 6912;
        const int k0 = i * 64;

        float S[8][4];
#pragma unroll
        for (int ii = 0; ii < 8; ii++)
#pragma unroll
            for (int j = 0; j < 4; j++) S[ii][j] = 0.f;
#pragma unroll
        for (int kk = 0; kk < 6; kk++) {
            unsigned bfr[8][2];
#pragma unroll
            for (int nf2 = 0; nf2 < 4; nf2++) {
                unsigned x0, x1, x2, x3;
                ldsm4(x0, x1, x2, x3, &sK[(nf2 * 16 + b_n) * 104 + kk * 16 + b_k]);
                bfr[2*nf2][0] = x0; bfr[2*nf2][1] = x1;
                bfr[2*nf2+1][0] = x2; bfr[2*nf2+1][1] = x3;
            }
#pragma unroll
            for (int nf = 0; nf < 8; nf++)
                mma16816(S[nf], aq[kk], bfr[nf]);
        }

#pragma unroll
        for (int nf = 0; nf < 8; nf++) {
            int c0 = cbase + 8 * nf;
            int g0 = k0 + c0, g1 = g0 + 1;
            unsigned t0 = sTab[g0], t1 = sTab[g1];
            if (g0 < NKV) {
                if (t0 >> 24) {
                    int kh_ = t0 & 255, kw_ = (t0 >> 8) & 255, kt_ = (t0 >> 16) & 255;
                    S[nf][0] += sEb[r0*24 + kh_] + sEb[r0*24 + 7 + kw_] + sEb[r0*24 + 14 + kt_];
                    S[nf][2] += sEb[r1*24 + kh_] + sEb[r1*24 + 7 + kw_] + sEb[r1*24 + 14 + kt_];
                }
            } else { S[nf][0] = -CUDART_INF_F; S[nf][2] = -CUDART_INF_F; }
            if (g1 < NKV) {
                if (t1 >> 24) {
                    int kh_ = t1 & 255, kw_ = (t1 >> 8) & 255, kt_ = (t1 >> 16) & 255;
                    S[nf][1] += sEb[r0*24 + kh_] + sEb[r0*24 + 7 + kw_] + sEb[r0*24 + 14 + kt_];
                    S[nf][3] += sEb[r1*24 + kh_] + sEb[r1*24 + 7 + kw_] + sEb[r1*24 + 14 + kt_];
                }
            } else { S[nf][1] = -CUDART_INF_F; S[nf][3] = -CUDART_INF_F; }
        }

        float mt0 = -CUDART_INF_F, mt1 = -CUDART_INF_F;
#pragma unroll
        for (int nf = 0; nf < 8; nf++) {
            mt0 = fmaxf(mt0, fmaxf(S[nf][0], S[nf][1]));
            mt1 = fmaxf(mt1, fmaxf(S[nf][2], S[nf][3]));
        }
        mt0 = fmaxf(mt0, __shfl_xor_sync(0xffffffffu, mt0, 1));
        mt0 = fmaxf(mt0, __shfl_xor_sync(0xffffffffu, mt0, 2));
        mt1 = fmaxf(mt1, __shfl_xor_sync(0xffffffffu, mt1, 1));
        mt1 = fmaxf(mt1, __shfl_xor_sync(0xffffffffu, mt1, 2));
        float mn0 = fmaxf(m0, mt0), mn1 = fmaxf(m1, mt1);
        float al0 = __expf(m0 - mn0), al1 = __expf(m1 - mn1);
        m0 = mn0; m1 = mn1;

        unsigned ap[4][4];
        float sum0 = 0.f, sum1 = 0.f;
#pragma unroll
        for (int kk = 0; kk < 4; kk++) {
            float p00 = __expf(S[2*kk][0] - m0),   p01 = __expf(S[2*kk][1] - m0);
            float p10 = __expf(S[2*kk][2] - m1),   p11 = __expf(S[2*kk][3] - m1);
            float q00 = __expf(S[2*kk+1][0] - m0), q01 = __expf(S[2*kk+1][1] - m0);
            float q10 = __expf(S[2*kk+1][2] - m1), q11 = __expf(S[2*kk+1][3] - m1);
            sum0 += p00 + p01 + q00 + q01;
            sum1 += p10 + p11 + q10 + q11;
            ap[kk][0] = pack_h2(p00, p01);
            ap[kk][1] = pack_h2(p10, p11);
            ap[kk][2] = pack_h2(q00, q01);
            ap[kk][3] = pack_h2(q10, q11);
        }
        sum0 += __shfl_xor_sync(0xffffffffu, sum0, 1);
        sum0 += __shfl_xor_sync(0xffffffffu, sum0, 2);
        sum1 += __shfl_xor_sync(0xffffffffu, sum1, 1);
        sum1 += __shfl_xor_sync(0xffffffffu, sum1, 2);
        l0 = l0 * al0 + sum0;
        l1 = l1 * al1 + sum1;
#pragma unroll
        for (int nf = 0; nf < 12; nf++) {
            o[nf][0] *= al0; o[nf][1] *= al0;
            o[nf][2] *= al1; o[nf][3] *= al1;
        }

#pragma unroll
        for (int kk = 0; kk < 4; kk++) {
#pragma unroll
            for (int nf2 = 0; nf2 < 6; nf2++) {
                unsigned x0, x1, x2, x3;
                ldsm4(x0, x1, x2, x3, &sVt[(nf2 * 16 + b_n) * 72 + kk * 16 + b_k]);
                unsigned bb0[2] = {x0, x1};
                unsigned bb1[2] = {x2, x3};
                mma16816(o[2*nf2],   ap[kk], bb0);
                mma16816(o[2*nf2+1], ap[kk], bb1);
            }
        }
        __syncthreads();

        if (i + 2 < 7) {
            const int k0n = (i + 2) * 64;
            __half* sKb = dsm + bf * 6656;
            __half* sVb = dsm + 13312 + bf * 6912;
            for (int j = t; j < 1536; j += 256) {
                if (j < 768) {
                    int r = j / 12, c = j - r * 12;
                    cpa16(sKb + r * 104 + c * 8, k16b + (size_t)(k0n + r) * 96 + c * 8);
                } else {
                    int q = j - 768; int r = q >> 3, c = q & 7;
                    cpa16(sVb + r * 72 + c * 8, v16b + (size_t)r * KPAD + k0n + c * 8);
                }
            }
            cpa_commit();
        }
    }

    const float inv0 = 1.f / l0, inv1 = 1.f / l1;
    const float* qpb = g_qp + (size_t)bh * NQ * 96;
    const int qg0 = q0 + r0, qg1 = q0 + r1;
    if (qg0 < NQ) {
#pragma unroll
        for (int nf = 0; nf < 12; nf++) {
            int c = cbase + 8 * nf;
            float v0 = o[nf][0] * inv0, v1 = o[nf][1] * inv0;
            if (qg0 > 0) {
                float2 rr = *(const float2*)&qpb[(size_t)qg0 * 96 + c];
                v0 += rr.x; v1 += rr.y;
            }
            *(__half2*)&g_ao16[((size_t)b * NQ + qg0) * 768 + h * 96 + c] = __floats2half2_rn(v0, v1);
        }
    }
    if (qg1 < NQ) {
#pragma unroll
        for (int nf = 0; nf < 12; nf++) {
            int c = cbase + 8 * nf;
            float v0 = o[nf][2] * inv1, v1 = o[nf][3] * inv1;
            if (qg1 > 0) {
                float2 rr = *(const float2*)&qpb[(size_t)qg1 * 96 + c];
                v0 += rr.x; v1 += rr.y;
            }
            *(__half2*)&g_ao16[((size_t)b * NQ + qg1) * 768 + h * 96 + c] = __floats2half2_rn(v0, v1);
        }
    }
}

// ============================================================
// launch
// ============================================================
extern "C" void kernel_launch(void* const* d_in, const int* in_sizes, int n_in,
                              void* d_out, int out_size)
{
    const float* x      = (const float*)d_in[0];
    const float* qkv_w  = (const float*)d_in[1];
    const float* qkv_b  = (const float*)d_in[2];
    const float* pw_q   = (const float*)d_in[3];
    const float* pw_k   = (const float*)d_in[4];
    const float* pw_v   = (const float*)d_in[5];
    const float* lnq_g  = (const float*)d_in[6];
    const float* lnq_b  = (const float*)d_in[7];
    const float* lnk_g  = (const float*)d_in[8];
    const float* lnk_b  = (const float*)d_in[9];
    const float* lnv_g  = (const float*)d_in[10];
    const float* lnv_b  = (const float*)d_in[11];
    const float* rel_h  = (const float*)d_in[12];
    const float* rel_w  = (const float*)d_in[13];
    const float* rel_t  = (const float*)d_in[14];
    const float* proj_w = (const float*)d_in[15];
    const float* proj_b = (const float*)d_in[16];
    float* out = (float*)d_out;

    const int attn_smem = (13312 + 13824) * (int)sizeof(__half);    // 54272
    cudaFuncSetAttribute(attn16_kernel, cudaFuncAttributeMaxDynamicSharedMemorySize, attn_smem);

    conv_x_kernel<<<(MROWS*DIMc/4 + 255)/256, 256>>>(x, MROWS*DIMc/4);
    convT_all_kernel<<<dim3(96, 24), 256>>>(qkv_w, proj_w);
    gemm16_qkv_kernel<<<dim3(18, 197), 256>>>(qkv_b);
    pool_ln_all_kernel<<<dim3(128, 297), 256>>>(pw_q, pw_k, pw_v,
                                                lnq_g, lnq_b, lnk_g, lnk_b, lnv_g, lnv_b);
    attn16_kernel<<<dim3(13, 128), 256, attn_smem>>>(rel_h, rel_w, rel_t);
    gemm16_proj_kernel<<<dim3(6, 197), 256>>>(proj_b, out);
}

// round 15
// speedup vs baseline: 1.5473x; 1.5473x over previous
#include <cuda_runtime.h>
#include <cuda_fp16.h>
#include <cstdint>
#include <math_constants.h>

// ---------------- problem constants ----------------
constexpr int B_   = 16;
constexpr int NH   = 8;
constexpr int NQ   = 1569;   // 8*14*14 + 1
constexpr int NKV  = 393;    // 8*7*7 + 1
constexpr int HDc  = 96;
constexpr int DIMc = 768;
constexpr int LQ   = 1568;
constexpr int MROWS = B_ * NQ;     // 25104
constexpr int QPAD = 1664;         // 13 * 128
constexpr int KPAD = 448;          // 7 * 64
constexpr float SCALE = 0.10206207261596577f;  // 96^-0.5

// ---------------- scratch (device globals; zero-initialized, no allocs) -----
__device__ float g_q [B_*NH*NQ*HDc];
__device__ float g_k [B_*NH*NQ*HDc];
__device__ float g_v [B_*NH*NQ*HDc];
__device__ float g_qp[B_*NH*NQ*HDc];
__device__ float g_kp[B_*NH*NKV*HDc];
__device__ float g_vp[B_*NH*NKV*HDc];
__device__ float g_E [B_*NH*LQ*22];
__device__ __half g_x16 [MROWS*DIMc];
__device__ __half g_w1T [3*DIMc*DIMc];
__device__ __half g_w2T [DIMc*DIMc];
__device__ __half g_ao16[MROWS*DIMc];
__device__ __half g_qp16[B_*NH*QPAD*HDc];   // pooled q fp16 (unscaled), padded rows zero
__device__ __half g_kp16[B_*NH*KPAD*HDc];   // pooled k fp16 * SCALE, padded rows zero
__device__ __half g_vp16t[B_*NH*HDc*KPAD];  // pooled v fp16 transposed [chan][key], pad zero

__device__ __forceinline__ float4 ld4(const float* p){ return *reinterpret_cast<const float4*>(p); }

// pack two floats -> half2 bits as unsigned (for mma A-fragment)
__device__ __forceinline__ unsigned pack_h2(float lo, float hi)
{
    __half2_raw hr = __floats2half2_rn(lo, hi);
    return (unsigned)hr.x | ((unsigned)hr.y << 16);
}

// ---------------- tensor-core helpers ----------------
__device__ __forceinline__ void ldsm4(unsigned int &r0, unsigned int &r1,
                                      unsigned int &r2, unsigned int &r3,
                                      const __half* p)
{
    unsigned int a = (unsigned int)__cvta_generic_to_shared(p);
    asm volatile("ldmatrix.sync.aligned.m8n8.x4.shared.b16 {%0,%1,%2,%3}, [%4];"
                 : "=r"(r0), "=r"(r1), "=r"(r2), "=r"(r3) : "r"(a));
}
__device__ __forceinline__ void mma16816(float* d, const unsigned int* a, const unsigned int* b)
{
    asm volatile("mma.sync.aligned.m16n8k16.row.col.f32.f16.f16.f32 "
                 "{%0,%1,%2,%3}, {%4,%5,%6,%7}, {%8,%9}, {%0,%1,%2,%3};"
                 : "+f"(d[0]), "+f"(d[1]), "+f"(d[2]), "+f"(d[3])
                 : "r"(a[0]), "r"(a[1]), "r"(a[2]), "r"(a[3]), "r"(b[0]), "r"(b[1]));
}
__device__ __forceinline__ void cpa16(const __half* sdst, const __half* gsrc)
{
    unsigned s = (unsigned)__cvta_generic_to_shared(sdst);
    asm volatile("cp.async.cg.shared.global [%0], [%1], 16;" :: "r"(s), "l"(gsrc) : "memory");
}
__device__ __forceinline__ void cpa_commit()
{
    asm volatile("cp.async.commit_group;" ::: "memory");
}

// ---------------- conversion kernels ----------------
__global__ __launch_bounds__(256) void conv_x_kernel(const float* __restrict__ x, int n4)
{
    int i = blockIdx.x * 256 + threadIdx.x;
    if (i >= n4) return;
    float4 v = reinterpret_cast<const float4*>(x)[i];
    reinterpret_cast<__half2*>(g_x16)[2*i]   = __floats2half2_rn(v.x, v.y);
    reinterpret_cast<__half2*>(g_x16)[2*i+1] = __floats2half2_rn(v.z, v.w);
}

// merged transpose-convert: blocks x<72 -> qkv_w (N=2304), x>=72 -> proj_w (N=768)
__global__ __launch_bounds__(256) void convT_all_kernel(
    const float* __restrict__ w1, const float* __restrict__ w2)
{
    __shared__ float tile[32][33];
    const int xb = blockIdx.x;
    const float* w;
    __half* wt;
    int N, n0;
    if (xb < 72) { w = w1; wt = g_w1T; N = 2304; n0 = xb * 32; }
    else         { w = w2; wt = g_w2T; N = 768;  n0 = (xb - 72) * 32; }
    int k0 = blockIdx.y * 32;
    int tx = threadIdx.x & 31, ty = (threadIdx.x >> 5) * 4;
#pragma unroll
    for (int i = 0; i < 4; i++)
        tile[ty + i][tx] = w[(size_t)(k0 + ty + i) * N + n0 + tx];
    __syncthreads();
#pragma unroll
    for (int i = 0; i < 4; i++)
        wt[(size_t)(n0 + ty + i) * 768 + k0 + tx] = __float2half(tile[tx][ty + i]);
}

// ============================================================
// fp16 tensor-core GEMM (R9 configuration: 2-stage cp.async,
// static smem, K-tile 32, 2 CTAs/SM) — measured best (369us qkv)
// ============================================================
template<int MODE>
__device__ __forceinline__ void gemm16_body(const float* __restrict__ bias, float* __restrict__ C)
{
    __shared__ __half As[2][128*40];
    __shared__ __half Bs[2][128*40];
    const __half* A  = (MODE == 0) ? g_x16 : g_ao16;
    const __half* BT = (MODE == 0) ? g_w1T : g_w2T;
    const int t = threadIdx.x;
    const int n0 = blockIdx.x * 128, m0 = blockIdx.y * 128;
    const int w = t >> 5, lane = t & 31;
    const int wr = w >> 1, wc = w & 1;
    const int arow = t >> 1, aseg = t & 1;

    const __half* Ag = A + (size_t)min(m0 + arow, MROWS - 1) * 768 + aseg * 16;
    const __half* Bg = BT + (size_t)(n0 + arow) * 768 + aseg * 16;
    __half* Adst = &As[0][0] + arow * 40 + aseg * 16;
    __half* Bdst = &Bs[0][0] + arow * 40 + aseg * 16;

    const int a_m = (lane & 7) + ((lane >> 3) & 1) * 8;
    const int a_k = ((lane >> 4) & 1) * 8;
    const int b_n = (lane & 7) + ((lane >> 4) & 1) * 8;
    const int b_k = ((lane >> 3) & 1) * 8;

    cpa16(Adst, Ag);           cpa16(Adst + 8, Ag + 8);
    cpa16(Bdst, Bg);           cpa16(Bdst + 8, Bg + 8);
    cpa_commit();

    float acc[2][8][4];
#pragma unroll
    for (int i = 0; i < 2; i++)
#pragma unroll
        for (int j = 0; j < 8; j++)
#pragma unroll
            for (int r = 0; r < 4; r++) acc[i][j][r] = 0.f;

    for (int kt = 0; kt < 24; kt++) {
        asm volatile("cp.async.wait_group 0;" ::: "memory");
        __syncthreads();
        if (kt < 23) {
            const int nb = (kt + 1) & 1;
            const __half* Ap = Ag + (kt + 1) * 32;
            const __half* Bp = Bg + (kt + 1) * 32;
            __half* Ad = Adst + nb * (128 * 40);
            __half* Bd = Bdst + nb * (128 * 40);
            cpa16(Ad, Ap); cpa16(Ad + 8, Ap + 8);
            cpa16(Bd, Bp); cpa16(Bd + 8, Bp + 8);
            cpa_commit();
        }
        const __half* Ab = &As[kt & 1][0];
        const __half* Bb = &Bs[kt & 1][0];
#pragma unroll
        for (int kk = 0; kk < 32; kk += 16) {
            unsigned int af[2][4];
            ldsm4(af[0][0], af[0][1], af[0][2], af[0][3],
                  Ab + (wr*32 + a_m) * 40 + kk + a_k);
            ldsm4(af[1][0], af[1][1], af[1][2], af[1][3],
                  Ab + (wr*32 + 16 + a_m) * 40 + kk + a_k);
            unsigned int bf[8][2];
#pragma unroll
            for (int nf2 = 0; nf2 < 4; nf2++) {
                unsigned int r0, r1, r2, r3;
                ldsm4(r0, r1, r2, r3, Bb + (wc*64 + nf2*16 + b_n) * 40 + kk + b_k);
                bf[2*nf2][0] = r0; bf[2*nf2][1] = r1;
                bf[2*nf2+1][0] = r2; bf[2*nf2+1][1] = r3;
            }
#pragma unroll
            for (int mf = 0; mf < 2; mf++)
#pragma unroll
                for (int nf = 0; nf < 8; nf++)
                    mma16816(acc[mf][nf], af[mf], bf[nf]);
        }
    }

    const int mbase = m0 + wr * 32 + (lane >> 2);
    const int nbase = n0 + wc * 64 + (lane & 3) * 2;
#pragma unroll
    for (int mf = 0; mf < 2; mf++) {
#pragma unroll
        for (int nf = 0; nf < 8; nf++) {
            const int n = nbase + nf * 8;
            const float2 bv = *(const float2*)&bias[n];
#pragma unroll
            for (int hh = 0; hh < 2; hh++) {
                const int m = mbase + mf * 16 + hh * 8;
                if (m >= MROWS) continue;
                float2 v2;
                v2.x = acc[mf][nf][2*hh]   + bv.x;
                v2.y = acc[mf][nf][2*hh+1] + bv.y;
                if (MODE == 0) {
                    const int qkvi = n / 768, rem = n - qkvi * 768;
                    const int head = rem / 96, c = rem - head * 96;
                    float* dst = (qkvi == 0) ? g_q : (qkvi == 1) ? g_k : g_v;
                    const int b_ = m / 1569, nn = m - b_ * 1569;
                    *(float2*)&dst[(((size_t)b_*8 + head)*1569 + nn)*96 + c] = v2;
                } else {
                    *(float2*)&C[(size_t)m * 768 + n] = v2;
                }
            }
        }
    }
}

__global__ __launch_bounds__(256, 2) void gemm16_qkv_kernel(const float* __restrict__ bias)
{
    gemm16_body<0>(bias, 0);
}

__global__ __launch_bounds__(256, 2) void gemm16_proj_kernel(const float* __restrict__ bias,
                                                             float* __restrict__ C)
{
    gemm16_body<1>(bias, C);
}

// ============================================================
// Attention pool + LN: merged q/k/v, 4 tokens per warp (32/block).
// grid.y: [0,50) -> q ; [50,63) -> k ; [63,76) -> v
// ============================================================
__global__ __launch_bounds__(256) void pool_ln_all_kernel(
    const float* __restrict__ wq, const float* __restrict__ wk, const float* __restrict__ wv,
    const float* __restrict__ gq, const float* __restrict__ bq,
    const float* __restrict__ gk, const float* __restrict__ bk,
    const float* __restrict__ gv, const float* __restrict__ bv)
{
    __shared__ float sw[96 * 27];
    __shared__ float sg[96], sb[96];
    const int bh = blockIdx.x;
    const int y  = blockIdx.y;
    const int t = threadIdx.x, warp = t >> 5, lane = t & 31;

    int sel, py0, outH, outW, stride, Nout;
    const float *w, *gamma, *beta;
    if (y < 50)      { sel = 0; py0 = y;      w = wq; gamma = gq; beta = bq; outH = 14; outW = 14; stride = 1; Nout = 1569; }
    else if (y < 63) { sel = 1; py0 = y - 50; w = wk; gamma = gk; beta = bk; outH = 7;  outW = 7;  stride = 2; Nout = 393;  }
    else             { sel = 2; py0 = y - 63; w = wv; gamma = gv; beta = bv; outH = 7;  outW = 7;  stride = 2; Nout = 393;  }

    for (int i = t; i < 96 * 27; i += 256) sw[i] = w[i];
    if (t < 96) { sg[t] = gamma[t]; sb[t] = beta[t]; }
    __syncthreads();

    const float* in  = (sel == 0) ? g_q : (sel == 1) ? g_k : g_v;
    float*       out = (sel == 0) ? g_qp : (sel == 1) ? g_kp : g_vp;
    const float* inb  = in  + (size_t)bh * NQ * 96;
    float*       outb = out + (size_t)bh * Nout * 96;

    const int c0 = lane, c1 = lane + 32, c2 = lane + 64;
    const int HW = outH * outW;
    const int p_base = py0 * 32 + warp * 4;

    for (int ii = 0; ii < 4; ii++) {
        const int p = p_base + ii;
        if (p >= Nout) break;
        float v0 = 0.f, v1 = 0.f, v2 = 0.f;
        if (p == 0) {
            v0 = inb[c0]; v1 = inb[c1]; v2 = inb[c2];
        } else {
            const int idx = p - 1;
            const int ot = idx / HW, r = idx - ot * HW;
            const int oh = r / outW, ow = r - oh * outW;
#pragma unroll
            for (int dt = 0; dt < 3; dt++) {
                int it = ot + dt - 1;
                if ((unsigned)it >= 8u) continue;
#pragma unroll
                for (int dh = 0; dh < 3; dh++) {
                    int ih = oh * stride + dh - 1;
                    if ((unsigned)ih >= 14u) continue;
#pragma unroll
                    for (int dw = 0; dw < 3; dw++) {
                        int iw = ow * stride + dw - 1;
                        if ((unsigned)iw >= 14u) continue;
                        const float* src = inb + (size_t)(1 + (it*14 + ih)*14 + iw) * 96;
                        const int wi = dt*9 + dh*3 + dw;
                        v0 += src[c0] * sw[c0*27 + wi];
                        v1 += src[c1] * sw[c1*27 + wi];
                        v2 += src[c2] * sw[c2*27 + wi];
                    }
                }
            }
        }

        float s1 = v0 + v1 + v2;
        float s2 = v0*v0 + v1*v1 + v2*v2;
#pragma unroll
        for (int off = 16; off; off >>= 1) {
            s1 += __shfl_xor_sync(0xffffffffu, s1, off);
            s2 += __shfl_xor_sync(0xffffffffu, s2, off);
        }
        const float mean = s1 * (1.f / 96.f);
        const float var  = s2 * (1.f / 96.f) - mean * mean;
        const float rstd = rsqrtf(var + 1e-5f);
        const float n0 = (v0 - mean) * rstd * sg[c0] + sb[c0];
        const float n1 = (v1 - mean) * rstd * sg[c1] + sb[c1];
        const float n2 = (v2 - mean) * rstd * sg[c2] + sb[c2];

        outb[(size_t)p * 96 + c0] = n0;
        outb[(size_t)p * 96 + c1] = n1;
        outb[(size_t)p * 96 + c2] = n2;

        if (sel == 0) {
            __half* q16 = g_qp16 + (size_t)bh * QPAD * 96 + (size_t)p * 96;
            q16[c0] = __float2half(n0); q16[c1] = __float2half(n1); q16[c2] = __float2half(n2);
        } else if (sel == 1) {
            __half* k16 = g_kp16 + (size_t)bh * KPAD * 96 + (size_t)p * 96;
            k16[c0] = __float2half(n0 * SCALE); k16[c1] = __float2half(n1 * SCALE); k16[c2] = __float2half(n2 * SCALE);
        } else {
            __half* v16 = g_vp16t + (size_t)bh * 96 * KPAD;
            v16[(size_t)c0 * KPAD + p] = __float2half(n0);
            v16[(size_t)c1 * KPAD + p] = __float2half(n1);
            v16[(size_t)c2 * KPAD + p] = __float2half(n2);
        }
    }
}

// ============================================================
// Rel-pos bias decomposition (restored R11 version)
// ============================================================
__global__ __launch_bounds__(256) void ebias_kernel(
    const float* __restrict__ rh, const float* __restrict__ rw, const float* __restrict__ rt)
{
    const int bh   = blockIdx.x;
    const int warp = threadIdx.x >> 5, lane = threadIdx.x & 31;
    const int p = blockIdx.y * 8 + warp;
    if (p >= LQ) return;
    const float* q = g_qp + ((size_t)bh * NQ + 1 + p) * 96;
    const float q0 = q[lane], q1 = q[lane + 32], q2 = q[lane + 64];
    const int t = p / 196, r = p - t * 196;
    const int hh = r / 14, ww = r - hh * 14;
    float* Eo = g_E + ((size_t)bh * LQ + p) * 22;

#pragma unroll
    for (int kh = 0; kh < 7; kh++) {
        const float* rr = rh + (hh - 2*kh + 12) * 96;
        float s = q0*rr[lane] + q1*rr[lane+32] + q2*rr[lane+64];
#pragma unroll
        for (int off = 16; off; off >>= 1) s += __shfl_xor_sync(0xffffffffu, s, off);
        if (lane == 0) Eo[kh] = s;
    }
#pragma unroll
    for (int kw = 0; kw < 7; kw++) {
        const float* rr = rw + (ww - 2*kw + 12) * 96;
        float s = q0*rr[lane] + q1*rr[lane+32] + q2*rr[lane+64];
#pragma unroll
        for (int off = 16; off; off >>= 1) s += __shfl_xor_sync(0xffffffffu, s, off);
        if (lane == 0) Eo[7 + kw] = s;
    }
#pragma unroll
    for (int kt = 0; kt < 8; kt++) {
        const float* rr = rt + (t - kt + 7) * 96;
        float s = q0*rr[lane] + q1*rr[lane+32] + q2*rr[lane+64];
#pragma unroll
        for (int off = 16; off; off >>= 1) s += __shfl_xor_sync(0xffffffffu, s, off);
        if (lane == 0) Eo[14 + kt] = s;
    }
}

// ============================================================
// fp16 flash attention: double-buffered cp.async K/V pipeline (R11)
// ============================================================
__global__ __launch_bounds__(256) void attn16_kernel()
{
    extern __shared__ __half dsm[];
    __shared__ float  sEb[128*24];
    __shared__ unsigned sTab[448];

    const int bh = blockIdx.y, b = bh >> 3, h = bh & 7;
    const int q0 = blockIdx.x * 128;
    const int t = threadIdx.x, w = t >> 5, lane = t & 31;

    for (int g = t; g < 448; g += 256) {
        unsigned v = 0;
        if (g >= 1 && g < NKV) {
            int kb = g - 1;
            int kt_ = kb / 49, r2 = kb - kt_ * 49;
            int kh_ = r2 / 7,  kw_ = r2 - kh_ * 7;
            v = (unsigned)kh_ | ((unsigned)kw_ << 8) | ((unsigned)kt_ << 16) | (1u << 24);
        }
        sTab[g] = v;
    }
    for (int i = t; i < 128 * 22; i += 256) {
        int q = i / 22, e = i - q * 22;
        int qg = q0 + q;
        sEb[q * 24 + e] = (qg >= 1 && qg < NQ) ? g_E[((size_t)bh * LQ + (qg - 1)) * 22 + e] : 0.f;
    }
    const __half* q16b = g_qp16 + (size_t)bh * QPAD * 96;
    for (int i = t; i < 128 * 12; i += 256) {
        int r = i / 12, s = i - r * 12;
        *(uint4*)&dsm[r * 104 + s * 8] = *(const uint4*)&q16b[(size_t)(q0 + r) * 96 + s * 8];
    }
    __syncthreads();

    const int a_m = (lane & 7) + ((lane >> 3) & 1) * 8;
    const int a_k = ((lane >> 4) & 1) * 8;
    const int b_n = (lane & 7) + ((lane >> 4) & 1) * 8;
    const int b_k = ((lane >> 3) & 1) * 8;

    unsigned aq[6][4];
#pragma unroll
    for (int kk = 0; kk < 6; kk++)
        ldsm4(aq[kk][0], aq[kk][1], aq[kk][2], aq[kk][3],
              &dsm[(w * 16 + a_m) * 104 + kk * 16 + a_k]);
    __syncthreads();

    const int r0 = w * 16 + (lane >> 2);
    const int r1 = r0 + 8;
    const int cbase = (lane & 3) * 2;

    float m0 = -CUDART_INF_F, m1 = -CUDART_INF_F, l0 = 0.f, l1 = 0.f;
    float o[12][4];
#pragma unroll
    for (int i = 0; i < 12; i++)
#pragma unroll
        for (int j = 0; j < 4; j++) o[i][j] = 0.f;

    const __half* k16b = g_kp16 + (size_t)bh * KPAD * 96;
    const __half* v16b = g_vp16t + (size_t)bh * 96 * KPAD;

#pragma unroll
    for (int pi = 0; pi < 2; pi++) {
        const int k0 = pi * 64;
        __half* sKb  = dsm + pi * 6656;
        __half* sVb  = dsm + 13312 + pi * 6912;
        for (int j = t; j < 1536; j += 256) {
            if (j < 768) {
                int r = j / 12, c = j - r * 12;
                cpa16(sKb + r * 104 + c * 8, k16b + (size_t)(k0 + r) * 96 + c * 8);
            } else {
                int q = j - 768; int r = q >> 3, c = q & 7;
                cpa16(sVb + r * 72 + c * 8, v16b + (size_t)r * KPAD + k0 + c * 8);
            }
        }
        cpa_commit();
    }

    for (int i = 0; i < 7; i++) {
        if (i == 6) asm volatile("cp.async.wait_group 0;" ::: "memory");
        else        asm volatile("cp.async.wait_group 1;" ::: "memory");
        __syncthreads();
        const int bf = i & 1;
        const __half* sK  = dsm + bf * 6656;
        const __half* sVt = dsm + 13312 + bf * 6912;
        const int k0 = i * 64;

        float S[8][4];
#pragma unroll
        for (int ii = 0; ii < 8; ii++)
#pragma unroll
            for (int j = 0; j < 4; j++) S[ii][j] = 0.f;
#pragma unroll
        for (int kk = 0; kk < 6; kk++) {
            unsigned bfr[8][2];
#pragma unroll
            for (int nf2 = 0; nf2 < 4; nf2++) {
                unsigned x0, x1, x2, x3;
                ldsm4(x0, x1, x2, x3, &sK[(nf2 * 16 + b_n) * 104 + kk * 16 + b_k]);
                bfr[2*nf2][0] = x0; bfr[2*nf2][1] = x1;
                bfr[2*nf2+1][0] = x2; bfr[2*nf2+1][1] = x3;
            }
#pragma unroll
            for (int nf = 0; nf < 8; nf++)
                mma16816(S[nf], aq[kk], bfr[nf]);
        }

#pragma unroll
        for (int nf = 0; nf < 8; nf++) {
            int c0 = cbase + 8 * nf;
            int g0 = k0 + c0, g1 = g0 + 1;
            unsigned t0 = sTab[g0], t1 = sTab[g1];
            if (g0 < NKV) {
                if (t0 >> 24) {
                    int kh_ = t0 & 255, kw_ = (t0 >> 8) & 255, kt_ = (t0 >> 16) & 255;
                    S[nf][0] += sEb[r0*24 + kh_] + sEb[r0*24 + 7 + kw_] + sEb[r0*24 + 14 + kt_];
                    S[nf][2] += sEb[r1*24 + kh_] + sEb[r1*24 + 7 + kw_] + sEb[r1*24 + 14 + kt_];
                }
            } else { S[nf][0] = -CUDART_INF_F; S[nf][2] = -CUDART_INF_F; }
            if (g1 < NKV) {
                if (t1 >> 24) {
                    int kh_ = t1 & 255, kw_ = (t1 >> 8) & 255, kt_ = (t1 >> 16) & 255;
                    S[nf][1] += sEb[r0*24 + kh_] + sEb[r0*24 + 7 + kw_] + sEb[r0*24 + 14 + kt_];
                    S[nf][3] += sEb[r1*24 + kh_] + sEb[r1*24 + 7 + kw_] + sEb[r1*24 + 14 + kt_];
                }
            } else { S[nf][1] = -CUDART_INF_F; S[nf][3] = -CUDART_INF_F; }
        }

        float mt0 = -CUDART_INF_F, mt1 = -CUDART_INF_F;
#pragma unroll
        for (int nf = 0; nf < 8; nf++) {
            mt0 = fmaxf(mt0, fmaxf(S[nf][0], S[nf][1]));
            mt1 = fmaxf(mt1, fmaxf(S[nf][2], S[nf][3]));
        }
        mt0 = fmaxf(mt0, __shfl_xor_sync(0xffffffffu, mt0, 1));
        mt0 = fmaxf(mt0, __shfl_xor_sync(0xffffffffu, mt0, 2));
        mt1 = fmaxf(mt1, __shfl_xor_sync(0xffffffffu, mt1, 1));
        mt1 = fmaxf(mt1, __shfl_xor_sync(0xffffffffu, mt1, 2));
        float mn0 = fmaxf(m0, mt0), mn1 = fmaxf(m1, mt1);
        float al0 = __expf(m0 - mn0), al1 = __expf(m1 - mn1);
        m0 = mn0; m1 = mn1;

        unsigned ap[4][4];
        float sum0 = 0.f, sum1 = 0.f;
#pragma unroll
        for (int kk = 0; kk < 4; kk++) {
            float p00 = __expf(S[2*kk][0] - m0),   p01 = __expf(S[2*kk][1] - m0);
            float p10 = __expf(S[2*kk][2] - m1),   p11 = __expf(S[2*kk][3] - m1);
            float q00 = __expf(S[2*kk+1][0] - m0), q01 = __expf(S[2*kk+1][1] - m0);
            float q10 = __expf(S[2*kk+1][2] - m1), q11 = __expf(S[2*kk+1][3] - m1);
            sum0 += p00 + p01 + q00 + q01;
            sum1 += p10 + p11 + q10 + q11;
            ap[kk][0] = pack_h2(p00, p01);
            ap[kk][1] = pack_h2(p10, p11);
            ap[kk][2] = pack_h2(q00, q01);
            ap[kk][3] = pack_h2(q10, q11);
        }
        sum0 += __shfl_xor_sync(0xffffffffu, sum0, 1);
        sum0 += __shfl_xor_sync(0xffffffffu, sum0, 2);
        sum1 += __shfl_xor_sync(0xffffffffu, sum1, 1);
        sum1 += __shfl_xor_sync(0xffffffffu, sum1, 2);
        l0 = l0 * al0 + sum0;
        l1 = l1 * al1 + sum1;
#pragma unroll
        for (int nf = 0; nf < 12; nf++) {
            o[nf][0] *= al0; o[nf][1] *= al0;
            o[nf][2] *= al1; o[nf][3] *= al1;
        }

#pragma unroll
        for (int kk = 0; kk < 4; kk++) {
#pragma unroll
            for (int nf2 = 0; nf2 < 6; nf2++) {
                unsigned x0, x1, x2, x3;
                ldsm4(x0, x1, x2, x3, &sVt[(nf2 * 16 + b_n) * 72 + kk * 16 + b_k]);
                unsigned bb0[2] = {x0, x1};
                unsigned bb1[2] = {x2, x3};
                mma16816(o[2*nf2],   ap[kk], bb0);
                mma16816(o[2*nf2+1], ap[kk], bb1);
            }
        }
        __syncthreads();

        if (i + 2 < 7) {
            const int k0n = (i + 2) * 64;
            __half* sKb = dsm + bf * 6656;
            __half* sVb = dsm + 13312 + bf * 6912;
            for (int j = t; j < 1536; j += 256) {
                if (j < 768) {
                    int r = j / 12, c = j - r * 12;
                    cpa16(sKb + r * 104 + c * 8, k16b + (size_t)(k0n + r) * 96 + c * 8);
                } else {
                    int q = j - 768; int r = q >> 3, c = q & 7;
                    cpa16(sVb + r * 72 + c * 8, v16b + (size_t)r * KPAD + k0n + c * 8);
                }
            }
            cpa_commit();
        }
    }

    const float inv0 = 1.f / l0, inv1 = 1.f / l1;
    const float* qpb = g_qp + (size_t)bh * NQ * 96;
    const int qg0 = q0 + r0, qg1 = q0 + r1;
    if (qg0 < NQ) {
#pragma unroll
        for (int nf = 0; nf < 12; nf++) {
            int c = cbase + 8 * nf;
            float v0 = o[nf][0] * inv0, v1 = o[nf][1] * inv0;
            if (qg0 > 0) {
                float2 rr = *(const float2*)&qpb[(size_t)qg0 * 96 + c];
                v0 += rr.x; v1 += rr.y;
            }
            *(__half2*)&g_ao16[((size_t)b * NQ + qg0) * 768 + h * 96 + c] = __floats2half2_rn(v0, v1);
        }
    }
    if (qg1 < NQ) {
#pragma unroll
        for (int nf = 0; nf < 12; nf++) {
            int c = cbase + 8 * nf;
            float v0 = o[nf][2] * inv1, v1 = o[nf][3] * inv1;
            if (qg1 > 0) {
                float2 rr = *(const float2*)&qpb[(size_t)qg1 * 96 + c];
                v0 += rr.x; v1 += rr.y;
            }
            *(__half2*)&g_ao16[((size_t)b * NQ + qg1) * 768 + h * 96 + c] = __floats2half2_rn(v0, v1);
        }
    }
}

// ============================================================
// launch
// ============================================================
extern "C" void kernel_launch(void* const* d_in, const int* in_sizes, int n_in,
                              void* d_out, int out_size)
{
    const float* x      = (const float*)d_in[0];
    const float* qkv_w  = (const float*)d_in[1];
    const float* qkv_b  = (const float*)d_in[2];
    const float* pw_q   = (const float*)d_in[3];
    const float* pw_k   = (const float*)d_in[4];
    const float* pw_v   = (const float*)d_in[5];
    const float* lnq_g  = (const float*)d_in[6];
    const float* lnq_b  = (const float*)d_in[7];
    const float* lnk_g  = (const float*)d_in[8];
    const float* lnk_b  = (const float*)d_in[9];
    const float* lnv_g  = (const float*)d_in[10];
    const float* lnv_b  = (const float*)d_in[11];
    const float* rel_h  = (const float*)d_in[12];
    const float* rel_w  = (const float*)d_in[13];
    const float* rel_t  = (const float*)d_in[14];
    const float* proj_w = (const float*)d_in[15];
    const float* proj_b = (const float*)d_in[16];
    float* out = (float*)d_out;

    const int attn_smem = (13312 + 13824) * (int)sizeof(__half);    // 54272
    cudaFuncSetAttribute(attn16_kernel, cudaFuncAttributeMaxDynamicSharedMemorySize, attn_smem);

    conv_x_kernel<<<(MROWS*DIMc/4 + 255)/256, 256>>>(x, MROWS*DIMc/4);
    convT_all_kernel<<<dim3(96, 24), 256>>>(qkv_w, proj_w);
    gemm16_qkv_kernel<<<dim3(18, 197), 256>>>(qkv_b);
    pool_ln_all_kernel<<<dim3(128, 76), 256>>>(pw_q, pw_k, pw_v,
                                               lnq_g, lnq_b, lnk_g, lnk_b, lnv_g, lnv_b);
    ebias_kernel<<<dim3(128, 196), 256>>>(rel_h, rel_w, rel_t);
    attn16_kernel<<<dim3(13, 128), 256, attn_smem>>>();
    gemm16_proj_kernel<<<dim3(6, 197), 256>>>(proj_b, out);
}